// round 16
// baseline (speedup 1.0000x reference)
#include <cuda_runtime.h>
#include <cuda_fp16.h>
#include <math.h>

#define NMAX 50000
#define EMAX 800000
#define DDIM 64

#define SBLK 1024
#define NSB ((NMAX + SBLK - 1) / SBLK)     // 49

// scratch (zero-initialized at load; invariants restored every run)
__device__ __half g_hh[(size_t)NMAX * DDIM];   // fp16 h (gather side)
__device__ int    g_cnt[NMAX];                 // degrees (zeroed by selu)
__device__ int    g_off[NMAX];                 // CSR offsets
__device__ int    g_fill[NMAX];                // fill cursors
__device__ unsigned long long g_aggf[NSB];     // scan aggregates (reset by fill)
__device__ uint4  g_edges[EMAX];               // (src, wbits, dst, pad), dst-grouped

// packed f32x2 FMA (FFMA2) — PTX-only; identical fp32 numerics.
#define FMA_F32X2(acc, a, b) \
    asm("fma.rn.f32x2 %0, %1, %2, %0;" : "+l"(acc) : "l"(a), "l"(b))
#define PACK_F32X2(out, lo, hi) \
    asm("mov.b64 %0, {%1, %2};" : "=l"(out) : "r"(lo), "r"(hi))
#define UNPACK_F32X2(lo, hi, in) \
    asm("mov.b64 {%0, %1}, %2;" : "=r"(lo), "=r"(hi) : "l"(in))

// ---------------------------------------------------------------------------
// Kernel 1: h = X @ W^T; out = h*skip + bias (fp32); g_hh = h (fp16);
// fused degree histogram.
// ---------------------------------------------------------------------------
#define XSTR 132
#define WSTR 68
#define GBLKS ((NMAX + 127) / 128)   // 391

__global__ void __launch_bounds__(256) gemm_skip_kernel(
    const float* __restrict__ X, const float* __restrict__ W,
    const float* __restrict__ bias, const float* __restrict__ skipw,
    const int* __restrict__ edst,
    float* __restrict__ out, int E, int n)
{
    __shared__ float sW[DDIM * WSTR];
    __shared__ float sX[DDIM * XSTR];

    const int tid  = threadIdx.x;
    const int row0 = blockIdx.x * 128;

    // fused histogram (fire-and-forget; g_cnt zero at entry)
    for (int i = blockIdx.x * 256 + tid; i < E; i += GBLKS * 256)
        atomicAdd(&g_cnt[edst[i]], 1);

    #pragma unroll
    for (int i = 0; i < 16; i++) {
        int idx = tid + i * 256;
        int o = idx >> 6, d = idx & 63;
        sW[d * WSTR + o] = W[idx];
    }
    #pragma unroll
    for (int i = 0; i < 32; i++) {
        int idx = tid + i * 256;
        int r = idx >> 6, d = idx & 63;
        int gr = row0 + r;
        sX[d * XSTR + r] = (gr < n) ? X[(size_t)gr * DDIM + d] : 0.0f;
    }
    __syncthreads();

    const int tx = tid & 15;
    const int ty = tid >> 4;
    const int o0 = tx * 4;
    const int r0 = ty * 8;

    unsigned long long accp[8][2];
    #pragma unroll
    for (int i = 0; i < 8; i++) { accp[i][0] = 0ULL; accp[i][1] = 0ULL; }

    #pragma unroll 16
    for (int d = 0; d < DDIM; d++) {
        float4 xa = *reinterpret_cast<const float4*>(&sX[d * XSTR + r0]);
        float4 xb = *reinterpret_cast<const float4*>(&sX[d * XSTR + r0 + 4]);
        ulonglong2 wp = *reinterpret_cast<const ulonglong2*>(&sW[d * WSTR + o0]);
        float x[8] = {xa.x, xa.y, xa.z, xa.w, xb.x, xb.y, xb.z, xb.w};
        #pragma unroll
        for (int i = 0; i < 8; i++) {
            unsigned xu = __float_as_uint(x[i]);
            unsigned long long xx;
            PACK_F32X2(xx, xu, xu);
            FMA_F32X2(accp[i][0], xx, wp.x);
            FMA_F32X2(accp[i][1], xx, wp.y);
        }
    }

    const float4 swv = *reinterpret_cast<const float4*>(&skipw[o0]);
    const float4 bvv = *reinterpret_cast<const float4*>(&bias[o0]);

    #pragma unroll
    for (int i = 0; i < 8; i++) {
        int gr = row0 + r0 + i;
        if (gr < n) {
            unsigned u0, u1, u2, u3;
            UNPACK_F32X2(u0, u1, accp[i][0]);
            UNPACK_F32X2(u2, u3, accp[i][1]);
            float4 hv = make_float4(__uint_as_float(u0), __uint_as_float(u1),
                                    __uint_as_float(u2), __uint_as_float(u3));
            __half2* dst2 = reinterpret_cast<__half2*>(&g_hh[(size_t)gr * DDIM + o0]);
            dst2[0] = __float22half2_rn(make_float2(hv.x, hv.y));
            dst2[1] = __float22half2_rn(make_float2(hv.z, hv.w));
            float4 ov;
            ov.x = fmaf(hv.x, swv.x, bvv.x);
            ov.y = fmaf(hv.y, swv.y, bvv.y);
            ov.z = fmaf(hv.z, swv.z, bvv.z);
            ov.w = fmaf(hv.w, swv.w, bvv.w);
            *reinterpret_cast<float4*>(&out[(size_t)gr * DDIM + o0]) = ov;
        }
    }
}

// ---------------------------------------------------------------------------
// Kernel 2: single-pass exclusive scan of g_cnt -> g_off / g_fill.
// ---------------------------------------------------------------------------
__global__ void __launch_bounds__(256) scan_kernel(int n)
{
    __shared__ int sv[256];
    __shared__ int sbase;
    const int b = blockIdx.x, t = threadIdx.x;
    const int base = b * SBLK + t * 4;

    int c[4];
    int s = 0;
    #pragma unroll
    for (int k = 0; k < 4; k++) {
        int i = base + k;
        c[k] = (i < n) ? g_cnt[i] : 0;
        s += c[k];
    }
    sv[t] = s;
    if (t == 0) sbase = 0;
    __syncthreads();
    #pragma unroll
    for (int off = 1; off < 256; off <<= 1) {
        int u = (t >= off) ? sv[t - off] : 0;
        __syncthreads();
        sv[t] += u;
        __syncthreads();
    }

    if (t == 0) {
        unsigned long long v = (1ULL << 32) | (unsigned)sv[255];
        atomicExch(&g_aggf[b], v);
    }
    __syncthreads();

    if (t < b) {
        unsigned long long v;
        do {
            v = *((volatile unsigned long long*)&g_aggf[t]);
        } while (!(v >> 32));
        atomicAdd(&sbase, (int)(unsigned)v);
    }
    __syncthreads();

    int run = sbase + sv[t] - s;
    #pragma unroll
    for (int k = 0; k < 4; k++) {
        int i = base + k;
        if (i < n) {
            g_off[i]  = run;
            g_fill[i] = run;
            run += c[k];
        }
    }
}

// ---------------------------------------------------------------------------
// Kernel 3: fill dst-grouped edge array (ONE STG.128 per edge);
// reset scan flags for next replay.
// ---------------------------------------------------------------------------
__global__ void fill_kernel(const int* __restrict__ src,
                            const int* __restrict__ dst,
                            const float* __restrict__ ew, int E)
{
    int i = blockIdx.x * blockDim.x + threadIdx.x;
    if (i < NSB) g_aggf[i] = 0ULL;
    if (i < E) {
        int d = dst[i];
        int slot = atomicAdd(&g_fill[d], 1);
        g_edges[slot] = make_uint4((unsigned)src[i], __float_as_uint(ew[i]),
                                   (unsigned)d, 0u);
    }
}

// ---------------------------------------------------------------------------
// Kernel 4: segmented scatter. dst-grouped edges; each 16-lane group walks
// 16 contiguous edges, register-accumulating while dst repeats, one red.v4
// per dst-change. All metas + flush flags register-staged BEFORE the reds
// (the red's memory clobber can't force smem re-reads).
// ---------------------------------------------------------------------------
#define EPB 256

__global__ void __launch_bounds__(256) scatter_seg_kernel(
    float* __restrict__ out, int E)
{
    __shared__ uint4 sm[EPB];

    const int tid  = threadIdx.x;
    const int base = blockIdx.x * EPB;

    int ge = base + tid;
    if (ge < E) sm[tid] = g_edges[ge];
    __syncthreads();

    const int grp   = tid >> 4;           // 0..15: which 16-edge run
    const int lane4 = (tid & 15) << 2;    // 0,4,...,60
    const int e0    = grp * 16;
    const int m     = min(E - base - e0, 16);
    if (m <= 0) return;

    float4 acc = make_float4(0.0f, 0.0f, 0.0f, 0.0f);

    #pragma unroll
    for (int b = 0; b < 2; b++) {
        const int cnt = min(m - b * 8, 8);
        if (cnt <= 0) break;

        // Phase 1: register-stage metas, flush flags, and 8 independent gathers
        uint4 ek[8];
        bool  fl[8];
        uint2 pk[8];
        #pragma unroll
        for (int q = 0; q < 8; q++) {
            const int k = b * 8 + q;
            ek[q] = (q < cnt) ? sm[e0 + k] : make_uint4(0u, 0u, 0u, 0u);
            // flush if last edge of run, or next edge has different dst
            fl[q] = (q < cnt) &&
                    ((k == m - 1) || (sm[e0 + k + 1].z != ek[q].z));
            pk[q] = *reinterpret_cast<const uint2*>(
                &g_hh[(size_t)ek[q].x * DDIM + lane4]);
        }

        // Phase 2: accumulate + conditional flush (registers only)
        #pragma unroll
        for (int q = 0; q < 8; q++) {
            if (q >= cnt) break;
            const float w = __uint_as_float(ek[q].y);
            float2 f0 = __half22float2(*reinterpret_cast<const __half2*>(&pk[q].x));
            float2 f1 = __half22float2(*reinterpret_cast<const __half2*>(&pk[q].y));
            acc.x = fmaf(f0.x, w, acc.x);
            acc.y = fmaf(f0.y, w, acc.y);
            acc.z = fmaf(f1.x, w, acc.z);
            acc.w = fmaf(f1.y, w, acc.w);

            if (fl[q]) {
                float* o = out + (size_t)ek[q].z * DDIM + lane4;
                asm volatile(
                    "red.global.add.v4.f32 [%0], {%1, %2, %3, %4};"
                    :: "l"(o), "f"(acc.x), "f"(acc.y), "f"(acc.z), "f"(acc.w)
                    : "memory");
                acc = make_float4(0.0f, 0.0f, 0.0f, 0.0f);
            }
        }
    }
}

// ---------------------------------------------------------------------------
// Kernel 5: in-place SELU; re-zeroes g_cnt for the next replay.
// ---------------------------------------------------------------------------
__global__ void __launch_bounds__(256) selu_kernel(float* __restrict__ out,
                                                   int total4, int n)
{
    const float scale = 1.0507009873554805f;
    const float alpha = 1.6732632423543772f;
    int i = blockIdx.x * blockDim.x + threadIdx.x;
    if (i < n) g_cnt[i] = 0;
    if (i >= total4) return;
    float4 v = reinterpret_cast<float4*>(out)[i];
    v.x = v.x > 0.0f ? scale * v.x : scale * alpha * (expf(v.x) - 1.0f);
    v.y = v.y > 0.0f ? scale * v.y : scale * alpha * (expf(v.y) - 1.0f);
    v.z = v.z > 0.0f ? scale * v.z : scale * alpha * (expf(v.z) - 1.0f);
    v.w = v.w > 0.0f ? scale * v.w : scale * alpha * (expf(v.w) - 1.0f);
    reinterpret_cast<float4*>(out)[i] = v;
}

extern "C" void kernel_launch(void* const* d_in, const int* in_sizes, int n_in,
                              void* d_out, int out_size)
{
    const float* features = (const float*)d_in[0];
    const float* W        = (const float*)d_in[1];
    const float* bias     = (const float*)d_in[2];
    const float* skipw    = (const float*)d_in[3];
    const float* ew       = (const float*)d_in[4];
    const int*   esrc     = (const int*)d_in[5];
    const int*   edst     = (const int*)d_in[6];
    float* out = (float*)d_out;

    const int n = in_sizes[0] / DDIM;     // 50000
    const int E = in_sizes[4];            // 800000

    // 1. GEMM + out-init (skip+bias) + fp16 copy + fused histogram
    gemm_skip_kernel<<<GBLKS, 256>>>(features, W, bias, skipw, edst, out, E, n);

    // 2. single-pass scan -> CSR offsets
    scan_kernel<<<NSB, 256>>>(n);

    // 3. group edges by dst (one 16B store per edge)
    fill_kernel<<<(E + 511) / 512, 512>>>(esrc, edst, ew, E);

    // 4. segmented scatter
    scatter_seg_kernel<<<(E + EPB - 1) / EPB, 256>>>(out, E);

    // 5. SELU in place + g_cnt reset
    int total4 = (n * DDIM) / 4;
    selu_kernel<<<(total4 + 255) / 256, 256>>>(out, total4, n);
}

// round 17
// speedup vs baseline: 1.0314x; 1.0314x over previous
#include <cuda_runtime.h>
#include <cuda_fp16.h>
#include <math.h>

#define NMAX 50000
#define EMAX 800000
#define DDIM 64

#define SBLK 1024
#define NSB ((NMAX + SBLK - 1) / SBLK)     // 49

// scratch (zero-initialized at load; invariants restored every run)
__device__ __half g_hh[(size_t)NMAX * DDIM];   // fp16 h (gather side)
__device__ int    g_cnt[NMAX];                 // degrees (zeroed by selu)
__device__ int    g_off[NMAX];                 // CSR offsets
__device__ int    g_fill[NMAX];                // fill cursors
__device__ unsigned long long g_aggf[NSB];     // scan aggregates (reset by fill)
__device__ uint2  g_edges[EMAX];               // packed (src|dst<<16, wbits), dst-grouped

// packed f32x2 FMA (FFMA2) — PTX-only; identical fp32 numerics.
#define FMA_F32X2(acc, a, b) \
    asm("fma.rn.f32x2 %0, %1, %2, %0;" : "+l"(acc) : "l"(a), "l"(b))
#define PACK_F32X2(out, lo, hi) \
    asm("mov.b64 %0, {%1, %2};" : "=l"(out) : "r"(lo), "r"(hi))
#define UNPACK_F32X2(lo, hi, in) \
    asm("mov.b64 {%0, %1}, %2;" : "=r"(lo), "=r"(hi) : "l"(in))

// ---------------------------------------------------------------------------
// Kernel 1: h = X @ W^T; out = h*skip + bias (fp32); g_hh = h (fp16);
// fused degree histogram.
// ---------------------------------------------------------------------------
#define XSTR 132
#define WSTR 68
#define GBLKS ((NMAX + 127) / 128)   // 391

__global__ void __launch_bounds__(256) gemm_skip_kernel(
    const float* __restrict__ X, const float* __restrict__ W,
    const float* __restrict__ bias, const float* __restrict__ skipw,
    const int* __restrict__ edst,
    float* __restrict__ out, int E, int n)
{
    __shared__ float sW[DDIM * WSTR];
    __shared__ float sX[DDIM * XSTR];

    const int tid  = threadIdx.x;
    const int row0 = blockIdx.x * 128;

    // fused histogram (fire-and-forget; g_cnt zero at entry)
    for (int i = blockIdx.x * 256 + tid; i < E; i += GBLKS * 256)
        atomicAdd(&g_cnt[edst[i]], 1);

    #pragma unroll
    for (int i = 0; i < 16; i++) {
        int idx = tid + i * 256;
        int o = idx >> 6, d = idx & 63;
        sW[d * WSTR + o] = W[idx];
    }
    #pragma unroll
    for (int i = 0; i < 32; i++) {
        int idx = tid + i * 256;
        int r = idx >> 6, d = idx & 63;
        int gr = row0 + r;
        sX[d * XSTR + r] = (gr < n) ? X[(size_t)gr * DDIM + d] : 0.0f;
    }
    __syncthreads();

    const int tx = tid & 15;
    const int ty = tid >> 4;
    const int o0 = tx * 4;
    const int r0 = ty * 8;

    unsigned long long accp[8][2];
    #pragma unroll
    for (int i = 0; i < 8; i++) { accp[i][0] = 0ULL; accp[i][1] = 0ULL; }

    #pragma unroll 16
    for (int d = 0; d < DDIM; d++) {
        float4 xa = *reinterpret_cast<const float4*>(&sX[d * XSTR + r0]);
        float4 xb = *reinterpret_cast<const float4*>(&sX[d * XSTR + r0 + 4]);
        ulonglong2 wp = *reinterpret_cast<const ulonglong2*>(&sW[d * WSTR + o0]);
        float x[8] = {xa.x, xa.y, xa.z, xa.w, xb.x, xb.y, xb.z, xb.w};
        #pragma unroll
        for (int i = 0; i < 8; i++) {
            unsigned xu = __float_as_uint(x[i]);
            unsigned long long xx;
            PACK_F32X2(xx, xu, xu);
            FMA_F32X2(accp[i][0], xx, wp.x);
            FMA_F32X2(accp[i][1], xx, wp.y);
        }
    }

    const float4 swv = *reinterpret_cast<const float4*>(&skipw[o0]);
    const float4 bvv = *reinterpret_cast<const float4*>(&bias[o0]);

    #pragma unroll
    for (int i = 0; i < 8; i++) {
        int gr = row0 + r0 + i;
        if (gr < n) {
            unsigned u0, u1, u2, u3;
            UNPACK_F32X2(u0, u1, accp[i][0]);
            UNPACK_F32X2(u2, u3, accp[i][1]);
            float4 hv = make_float4(__uint_as_float(u0), __uint_as_float(u1),
                                    __uint_as_float(u2), __uint_as_float(u3));
            __half2* dst2 = reinterpret_cast<__half2*>(&g_hh[(size_t)gr * DDIM + o0]);
            dst2[0] = __float22half2_rn(make_float2(hv.x, hv.y));
            dst2[1] = __float22half2_rn(make_float2(hv.z, hv.w));
            float4 ov;
            ov.x = fmaf(hv.x, swv.x, bvv.x);
            ov.y = fmaf(hv.y, swv.y, bvv.y);
            ov.z = fmaf(hv.z, swv.z, bvv.z);
            ov.w = fmaf(hv.w, swv.w, bvv.w);
            *reinterpret_cast<float4*>(&out[(size_t)gr * DDIM + o0]) = ov;
        }
    }
}

// ---------------------------------------------------------------------------
// Kernel 2: single-pass exclusive scan of g_cnt -> g_off / g_fill.
// ---------------------------------------------------------------------------
__global__ void __launch_bounds__(256) scan_kernel(int n)
{
    __shared__ int sv[256];
    __shared__ int sbase;
    const int b = blockIdx.x, t = threadIdx.x;
    const int base = b * SBLK + t * 4;

    int c[4];
    int s = 0;
    #pragma unroll
    for (int k = 0; k < 4; k++) {
        int i = base + k;
        c[k] = (i < n) ? g_cnt[i] : 0;
        s += c[k];
    }
    sv[t] = s;
    if (t == 0) sbase = 0;
    __syncthreads();
    #pragma unroll
    for (int off = 1; off < 256; off <<= 1) {
        int u = (t >= off) ? sv[t - off] : 0;
        __syncthreads();
        sv[t] += u;
        __syncthreads();
    }

    if (t == 0) {
        unsigned long long v = (1ULL << 32) | (unsigned)sv[255];
        atomicExch(&g_aggf[b], v);
    }
    __syncthreads();

    if (t < b) {
        unsigned long long v;
        do {
            v = *((volatile unsigned long long*)&g_aggf[t]);
        } while (!(v >> 32));
        atomicAdd(&sbase, (int)(unsigned)v);
    }
    __syncthreads();

    int run = sbase + sv[t] - s;
    #pragma unroll
    for (int k = 0; k < 4; k++) {
        int i = base + k;
        if (i < n) {
            g_off[i]  = run;
            g_fill[i] = run;
            run += c[k];
        }
    }
}

// ---------------------------------------------------------------------------
// Kernel 3: fill dst-grouped packed edge array (ONE 8B store per edge);
// reset scan flags for next replay.
// ---------------------------------------------------------------------------
__global__ void fill_kernel(const int* __restrict__ src,
                            const int* __restrict__ dst,
                            const float* __restrict__ ew, int E)
{
    int i = blockIdx.x * blockDim.x + threadIdx.x;
    if (i < NSB) g_aggf[i] = 0ULL;
    if (i < E) {
        int d = dst[i];
        int slot = atomicAdd(&g_fill[d], 1);
        g_edges[slot] = make_uint2((unsigned)src[i] | ((unsigned)d << 16),
                                   __float_as_uint(ew[i]));
    }
}

// ---------------------------------------------------------------------------
// Kernel 4: segmented scatter over dst-grouped packed edges.
// Each 16-lane group walks 16 contiguous edges, register-accumulating while
// dst repeats, one red.v4 per dst-change (~2 per run). No "memory" clobber
// on the red: inputs are registers and this kernel never reads `out`, so
// the compiler may schedule gathers freely across flushes.
// ---------------------------------------------------------------------------
#define EPB 256

__global__ void __launch_bounds__(256) scatter_seg_kernel(
    float* __restrict__ out, int E)
{
    __shared__ uint2 sm[EPB];

    const int tid  = threadIdx.x;
    const int base = blockIdx.x * EPB;

    int ge = base + tid;
    if (ge < E) sm[tid] = g_edges[ge];
    __syncthreads();

    const int grp   = tid >> 4;           // 0..15: which 16-edge run
    const int lane4 = (tid & 15) << 2;    // 0,4,...,60
    const int e0    = grp * 16;
    const int m     = min(E - base - e0, 16);
    if (m <= 0) return;

    float4 acc = make_float4(0.0f, 0.0f, 0.0f, 0.0f);

    #pragma unroll
    for (int b = 0; b < 2; b++) {
        const int cnt = min(m - b * 8, 8);
        if (cnt <= 0) break;

        // Phase 1: up to 8 independent gathers (8B fp16 each)
        uint2 pk[8];
        #pragma unroll
        for (int q = 0; q < 8; q++) {
            unsigned s = (q < cnt) ? (sm[e0 + b * 8 + q].x & 0xFFFFu) : 0u;
            pk[q] = *reinterpret_cast<const uint2*>(
                &g_hh[(size_t)s * DDIM + lane4]);
        }

        // Phase 2: accumulate; flush on dst-change or run end
        #pragma unroll
        for (int q = 0; q < 8; q++) {
            if (q >= cnt) break;
            const int k = b * 8 + q;
            const uint2 mm = sm[e0 + k];
            const float w = __uint_as_float(mm.y);
            float2 f0 = __half22float2(*reinterpret_cast<const __half2*>(&pk[q].x));
            float2 f1 = __half22float2(*reinterpret_cast<const __half2*>(&pk[q].y));
            acc.x = fmaf(f0.x, w, acc.x);
            acc.y = fmaf(f0.y, w, acc.y);
            acc.z = fmaf(f1.x, w, acc.z);
            acc.w = fmaf(f1.y, w, acc.w);

            const unsigned d = mm.x >> 16;
            const bool flush = (k == m - 1) || ((sm[e0 + k + 1].x >> 16) != d);
            if (flush) {
                float* o = out + (size_t)d * DDIM + lane4;
                asm volatile(
                    "red.global.add.v4.f32 [%0], {%1, %2, %3, %4};"
                    :: "l"(o), "f"(acc.x), "f"(acc.y), "f"(acc.z), "f"(acc.w));
                acc = make_float4(0.0f, 0.0f, 0.0f, 0.0f);
            }
        }
    }
}

// ---------------------------------------------------------------------------
// Kernel 5: in-place SELU; re-zeroes g_cnt for the next replay.
// ---------------------------------------------------------------------------
__global__ void __launch_bounds__(256) selu_kernel(float* __restrict__ out,
                                                   int total4, int n)
{
    const float scale = 1.0507009873554805f;
    const float alpha = 1.6732632423543772f;
    int i = blockIdx.x * blockDim.x + threadIdx.x;
    if (i < n) g_cnt[i] = 0;
    if (i >= total4) return;
    float4 v = reinterpret_cast<float4*>(out)[i];
    v.x = v.x > 0.0f ? scale * v.x : scale * alpha * (expf(v.x) - 1.0f);
    v.y = v.y > 0.0f ? scale * v.y : scale * alpha * (expf(v.y) - 1.0f);
    v.z = v.z > 0.0f ? scale * v.z : scale * alpha * (expf(v.z) - 1.0f);
    v.w = v.w > 0.0f ? scale * v.w : scale * alpha * (expf(v.w) - 1.0f);
    reinterpret_cast<float4*>(out)[i] = v;
}

extern "C" void kernel_launch(void* const* d_in, const int* in_sizes, int n_in,
                              void* d_out, int out_size)
{
    const float* features = (const float*)d_in[0];
    const float* W        = (const float*)d_in[1];
    const float* bias     = (const float*)d_in[2];
    const float* skipw    = (const float*)d_in[3];
    const float* ew       = (const float*)d_in[4];
    const int*   esrc     = (const int*)d_in[5];
    const int*   edst     = (const int*)d_in[6];
    float* out = (float*)d_out;

    const int n = in_sizes[0] / DDIM;     // 50000
    const int E = in_sizes[4];            // 800000

    // 1. GEMM + out-init (skip+bias) + fp16 copy + fused histogram
    gemm_skip_kernel<<<GBLKS, 256>>>(features, W, bias, skipw, edst, out, E, n);

    // 2. single-pass scan -> CSR offsets
    scan_kernel<<<NSB, 256>>>(n);

    // 3. group edges by dst (one 8B store per edge, packed record)
    fill_kernel<<<(E + 511) / 512, 512>>>(esrc, edst, ew, E);

    // 4. segmented scatter
    scatter_seg_kernel<<<(E + EPB - 1) / EPB, 256>>>(out, E);

    // 5. SELU in place + g_cnt reset
    int total4 = (n * DDIM) / 4;
    selu_kernel<<<(total4 + 255) / 256, 256>>>(out, total4, n);
}